// round 1
// baseline (speedup 1.0000x reference)
#include <cuda_runtime.h>

// Problem constants
#define HID   1024
#define NHEAD 16
#define DKDIM 64
#define SEQ   2048
#define BATCH 2
#define MROWS (BATCH * SEQ)      // 4096
#define HEADSZ (SEQ * DKDIM)     // 131072 floats per (b,h) head

// Scratch (allocation-free rule: __device__ globals)
__device__ float g_Q[MROWS * HID];   // head-major [B*NH][SEQ][DK]
__device__ float g_K[MROWS * HID];
__device__ float g_V[MROWS * HID];
__device__ float g_M[MROWS * HID];   // merged attention output [MROWS][HID]

// ---------------------------------------------------------------------------
// SGEMM: C[M,N] = A[M,K=1024] * W[1024,N] + bias, 128x128x8 tile, 8x8/thread
// ---------------------------------------------------------------------------
#define GBM 128
#define GBN 128
#define GBK 8

template<bool HEAD_MAJOR>
__device__ __forceinline__ void sgemm_tile(const float* __restrict__ A,
                                           const float* __restrict__ W,
                                           const float* __restrict__ bias,
                                           float* __restrict__ out, int N) {
    __shared__ float As[GBK][GBM];
    __shared__ float Bs[GBK][GBN];
    const int tid = threadIdx.x;
    const int tx = tid & 15, ty = tid >> 4;
    const int row0 = blockIdx.y * GBM;
    const int col0 = blockIdx.x * GBN;

    // A tile loader: each thread one float4 (row = tid/2, k-offset = (tid&1)*4)
    const int a_row = tid >> 1;
    const int a_k4  = (tid & 1) * 4;
    // B tile loader: row = tid/32 (k), col = (tid&31)*4
    const int b_k  = tid >> 5;
    const int b_n4 = (tid & 31) * 4;

    float acc[8][8];
#pragma unroll
    for (int i = 0; i < 8; i++)
#pragma unroll
        for (int j = 0; j < 8; j++) acc[i][j] = 0.f;

    const float* Aptr = A + (size_t)(row0 + a_row) * HID + a_k4;
    const float* Wptr = W + (size_t)b_k * N + col0 + b_n4;

    for (int k0 = 0; k0 < HID; k0 += GBK) {
        float4 av = *(const float4*)(Aptr + k0);
        As[a_k4 + 0][a_row] = av.x;
        As[a_k4 + 1][a_row] = av.y;
        As[a_k4 + 2][a_row] = av.z;
        As[a_k4 + 3][a_row] = av.w;
        *(float4*)&Bs[b_k][b_n4] = *(const float4*)(Wptr + (size_t)k0 * N);
        __syncthreads();
#pragma unroll
        for (int k = 0; k < GBK; k++) {
            float4 a0 = *(const float4*)&As[k][ty * 8];
            float4 a1 = *(const float4*)&As[k][ty * 8 + 4];
            float4 b0 = *(const float4*)&Bs[k][tx * 8];
            float4 b1 = *(const float4*)&Bs[k][tx * 8 + 4];
            float ra[8] = {a0.x, a0.y, a0.z, a0.w, a1.x, a1.y, a1.z, a1.w};
            float rb[8] = {b0.x, b0.y, b0.z, b0.w, b1.x, b1.y, b1.z, b1.w};
#pragma unroll
            for (int i = 0; i < 8; i++)
#pragma unroll
                for (int j = 0; j < 8; j++)
                    acc[i][j] = fmaf(ra[i], rb[j], acc[i][j]);
        }
        __syncthreads();
    }

#pragma unroll
    for (int i = 0; i < 8; i++) {
        int m = row0 + ty * 8 + i;
        int b = m >> 11, s = m & 2047;   // SEQ = 2048
#pragma unroll
        for (int j = 0; j < 8; j++) {
            int n = col0 + tx * 8 + j;
            float v = acc[i][j] + bias[n];
            if (HEAD_MAJOR) {
                int hh = n >> 6, d = n & 63;   // DK = 64
                out[((size_t)((b << 4) + hh) << 17) + ((size_t)s << 6) + d] = v;
            } else {
                out[(size_t)m * N + n] = v;
            }
        }
    }
}

__global__ __launch_bounds__(256) void qkv_gemm_kernel(
    const float* q, const float* k, const float* v,
    const float* Wq, const float* bq,
    const float* Wk, const float* bk,
    const float* Wv, const float* bv) {
    const float *A, *W, *bias;
    float* out;
    if (blockIdx.z == 0)      { A = q; W = Wq; bias = bq; out = g_Q; }
    else if (blockIdx.z == 1) { A = k; W = Wk; bias = bk; out = g_K; }
    else                      { A = v; W = Wv; bias = bv; out = g_V; }
    sgemm_tile<true>(A, W, bias, out, HID);
}

__global__ __launch_bounds__(256) void out_gemm_kernel(
    const float* Wo, const float* bo,
    const float* Wc, const float* bc, float* out) {
    const float *W, *bias;
    float* o;
    if (blockIdx.z == 0) { W = Wc; bias = bc; o = out; }                        // c first
    else                 { W = Wo; bias = bo; o = out + (size_t)MROWS * HID; }  // then h
    sgemm_tile<false>(g_M, W, bias, o, HID);
}

// ---------------------------------------------------------------------------
// Flash attention: per (b,h), 64-query blocks, 32-key tiles, online softmax.
// 256 threads = 16x16; scores 4q x 2k per thread; PV 4q x 4d per thread.
// ---------------------------------------------------------------------------
__global__ __launch_bounds__(256) void attn_kernel() {
    __shared__ float Qs[64][68];
    __shared__ float Ks[32][68];
    __shared__ float Vs[32][68];
    __shared__ float Ss[64][36];
    __shared__ float mrow[64], lrow[64], arow[64];

    const int bh = blockIdx.y;
    const int q0 = blockIdx.x * 64;
    const float* Qh = g_Q + (size_t)bh * HEADSZ;
    const float* Kh = g_K + (size_t)bh * HEADSZ;
    const float* Vh = g_V + (size_t)bh * HEADSZ;
    const int tid = threadIdx.x;
    const int tx = tid & 15, ty = tid >> 4;

    // Load Q tile (scaled by 1/sqrt(DK) = 0.125)
    for (int i = tid; i < 64 * 16; i += 256) {
        int r = i >> 4, c4 = (i & 15) << 2;
        float4 v = *(const float4*)(Qh + (size_t)(q0 + r) * DKDIM + c4);
        Qs[r][c4 + 0] = v.x * 0.125f;
        Qs[r][c4 + 1] = v.y * 0.125f;
        Qs[r][c4 + 2] = v.z * 0.125f;
        Qs[r][c4 + 3] = v.w * 0.125f;
    }
    if (tid < 64) { mrow[tid] = -1e30f; lrow[tid] = 0.f; }

    float acc[4][4];
#pragma unroll
    for (int i = 0; i < 4; i++)
#pragma unroll
        for (int j = 0; j < 4; j++) acc[i][j] = 0.f;
    __syncthreads();

    for (int k0 = 0; k0 < SEQ; k0 += 32) {
        // load K,V tiles: 32x64 each
        for (int i = tid; i < 32 * 16; i += 256) {
            int r = i >> 4, c4 = (i & 15) << 2;
            *(float4*)&Ks[r][c4] = *(const float4*)(Kh + (size_t)(k0 + r) * DKDIM + c4);
            *(float4*)&Vs[r][c4] = *(const float4*)(Vh + (size_t)(k0 + r) * DKDIM + c4);
        }
        __syncthreads();

        // Phase A: scores S = Qs * Ks^T  (4q x 2k per thread)
        {
            const int qb = ty * 4, kb = tx * 2;
            float s00 = 0, s01 = 0, s10 = 0, s11 = 0;
            float s20 = 0, s21 = 0, s30 = 0, s31 = 0;
#pragma unroll 8
            for (int d = 0; d < DKDIM; d++) {
                float b0 = Ks[kb][d], b1 = Ks[kb + 1][d];
                float a0 = Qs[qb + 0][d]; s00 = fmaf(a0, b0, s00); s01 = fmaf(a0, b1, s01);
                float a1 = Qs[qb + 1][d]; s10 = fmaf(a1, b0, s10); s11 = fmaf(a1, b1, s11);
                float a2 = Qs[qb + 2][d]; s20 = fmaf(a2, b0, s20); s21 = fmaf(a2, b1, s21);
                float a3 = Qs[qb + 3][d]; s30 = fmaf(a3, b0, s30); s31 = fmaf(a3, b1, s31);
            }
            Ss[qb + 0][kb] = s00; Ss[qb + 0][kb + 1] = s01;
            Ss[qb + 1][kb] = s10; Ss[qb + 1][kb + 1] = s11;
            Ss[qb + 2][kb] = s20; Ss[qb + 2][kb + 1] = s21;
            Ss[qb + 3][kb] = s30; Ss[qb + 3][kb + 1] = s31;
        }
        __syncthreads();

        // Phase B: online softmax update (one thread per query row)
        if (tid < 64) {
            float mo = mrow[tid], m = mo;
#pragma unroll
            for (int j = 0; j < 32; j++) m = fmaxf(m, Ss[tid][j]);
            float alpha = __expf(mo - m);
            float sum = 0.f;
#pragma unroll
            for (int j = 0; j < 32; j++) {
                float p = __expf(Ss[tid][j] - m);
                Ss[tid][j] = p;
                sum += p;
            }
            lrow[tid] = lrow[tid] * alpha + sum;
            mrow[tid] = m;
            arow[tid] = alpha;
        }
        __syncthreads();

        // Phase C: acc = acc*alpha + P * V  (4q x 4d per thread)
        {
            const int qb = ty * 4, db = tx * 4;
            float al0 = arow[qb], al1 = arow[qb + 1], al2 = arow[qb + 2], al3 = arow[qb + 3];
#pragma unroll
            for (int j = 0; j < 4; j++) {
                acc[0][j] *= al0; acc[1][j] *= al1;
                acc[2][j] *= al2; acc[3][j] *= al3;
            }
#pragma unroll 4
            for (int j = 0; j < 32; j++) {
                float4 vv = *(const float4*)&Vs[j][db];
                float p0 = Ss[qb + 0][j], p1 = Ss[qb + 1][j];
                float p2 = Ss[qb + 2][j], p3 = Ss[qb + 3][j];
                acc[0][0] = fmaf(p0, vv.x, acc[0][0]); acc[0][1] = fmaf(p0, vv.y, acc[0][1]);
                acc[0][2] = fmaf(p0, vv.z, acc[0][2]); acc[0][3] = fmaf(p0, vv.w, acc[0][3]);
                acc[1][0] = fmaf(p1, vv.x, acc[1][0]); acc[1][1] = fmaf(p1, vv.y, acc[1][1]);
                acc[1][2] = fmaf(p1, vv.z, acc[1][2]); acc[1][3] = fmaf(p1, vv.w, acc[1][3]);
                acc[2][0] = fmaf(p2, vv.x, acc[2][0]); acc[2][1] = fmaf(p2, vv.y, acc[2][1]);
                acc[2][2] = fmaf(p2, vv.z, acc[2][2]); acc[2][3] = fmaf(p2, vv.w, acc[2][3]);
                acc[3][0] = fmaf(p3, vv.x, acc[3][0]); acc[3][1] = fmaf(p3, vv.y, acc[3][1]);
                acc[3][2] = fmaf(p3, vv.z, acc[3][2]); acc[3][3] = fmaf(p3, vv.w, acc[3][3]);
            }
        }
        __syncthreads();
    }

    // Normalize and write merged [MROWS][HID]: col = h*64 + d
    {
        const int qb = ty * 4, db = tx * 4;
        const int b = bh >> 4, hh = bh & 15;
#pragma unroll
        for (int i = 0; i < 4; i++) {
            float inv = 1.0f / lrow[qb + i];
            float4 o;
            o.x = acc[i][0] * inv; o.y = acc[i][1] * inv;
            o.z = acc[i][2] * inv; o.w = acc[i][3] * inv;
            *(float4*)(g_M + (size_t)(b * SEQ + q0 + qb + i) * HID + hh * DKDIM + db) = o;
        }
    }
}

// ---------------------------------------------------------------------------
extern "C" void kernel_launch(void* const* d_in, const int* in_sizes, int n_in,
                              void* d_out, int out_size) {
    const float* q  = (const float*)d_in[0];
    const float* k  = (const float*)d_in[1];
    const float* v  = (const float*)d_in[2];
    const float* Wq = (const float*)d_in[3];
    const float* bq = (const float*)d_in[4];
    const float* Wk = (const float*)d_in[5];
    const float* bk = (const float*)d_in[6];
    const float* Wv = (const float*)d_in[7];
    const float* bv = (const float*)d_in[8];
    const float* Wo = (const float*)d_in[9];
    const float* bo = (const float*)d_in[10];
    const float* Wc = (const float*)d_in[11];
    const float* bc = (const float*)d_in[12];
    float* out = (float*)d_out;

    dim3 g1(HID / GBN, MROWS / GBM, 3);
    qkv_gemm_kernel<<<g1, 256>>>(q, k, v, Wq, bq, Wk, bk, Wv, bv);

    attn_kernel<<<dim3(SEQ / 64, BATCH * NHEAD), 256>>>();

    dim3 g2(HID / GBN, MROWS / GBM, 2);
    out_gemm_kernel<<<g2, 256>>>(Wo, bo, Wc, bc, out);
}

// round 7
// speedup vs baseline: 1.1026x; 1.1026x over previous
#include <cuda_runtime.h>
#include <cstdint>

// Problem constants
#define HID   1024
#define NHEAD 16
#define DKDIM 64
#define SEQ   2048
#define BATCH 2
#define MROWS (BATCH * SEQ)      // 4096
#define HEADSZ (SEQ * DKDIM)     // 131072 floats per (b,h) head

// Scratch (allocation-free rule: __device__ globals)
__device__ float g_Q[MROWS * HID];   // head-major [B*NH][SEQ][DK]
__device__ float g_K[MROWS * HID];
__device__ float g_V[MROWS * HID];
__device__ float g_M[MROWS * HID];   // merged attention output [MROWS][HID]

// ---------------------------------------------------------------------------
// SGEMM: C[M,N] = A[M,K=1024] * W[1024,N] + bias
// 128x128 tile, GBK=16, register-staged double buffer, 1 sync per chunk.
// ---------------------------------------------------------------------------
#define GBM 128
#define GBN 128
#define GBK 16
#define NKCH (HID / GBK)   // 64

template<bool HEAD_MAJOR>
__device__ __forceinline__ void sgemm_tile(const float* __restrict__ A,
                                           const float* __restrict__ W,
                                           const float* __restrict__ bias,
                                           float* __restrict__ out, int N) {
    __shared__ float As[2][GBK][GBM];   // 16 KB
    __shared__ float Bs[2][GBK][GBN];   // 16 KB
    const int tid = threadIdx.x;
    const int tx = tid & 15, ty = tid >> 4;
    const int row0 = blockIdx.y * GBM;
    const int col0 = blockIdx.x * GBN;

    // A loader: row = tid/2, k-offset = (tid&1)*8, two float4s
    const int a_row = tid >> 1;
    const int a_k8  = (tid & 1) * 8;
    // B loader: k-row = tid/16 (0..15), n-offset = (tid&15)*8, two float4s
    const int b_k  = tid >> 4;
    const int b_n8 = (tid & 15) * 8;

    const float* Aptr = A + (size_t)(row0 + a_row) * HID + a_k8;
    const float* Wptr = W + col0 + b_n8;   // + k*N per chunk

    float acc[8][8];
#pragma unroll
    for (int i = 0; i < 8; i++)
#pragma unroll
        for (int j = 0; j < 8; j++) acc[i][j] = 0.f;

    // preamble: chunk 0 -> smem[0]
    {
        float4 ra0 = *(const float4*)(Aptr + 0);
        float4 ra1 = *(const float4*)(Aptr + 4);
        float4 rb0 = *(const float4*)(Wptr + (size_t)b_k * N);
        float4 rb1 = *(const float4*)(Wptr + (size_t)b_k * N + 4);
        As[0][a_k8 + 0][a_row] = ra0.x; As[0][a_k8 + 1][a_row] = ra0.y;
        As[0][a_k8 + 2][a_row] = ra0.z; As[0][a_k8 + 3][a_row] = ra0.w;
        As[0][a_k8 + 4][a_row] = ra1.x; As[0][a_k8 + 5][a_row] = ra1.y;
        As[0][a_k8 + 6][a_row] = ra1.z; As[0][a_k8 + 7][a_row] = ra1.w;
        *(float4*)&Bs[0][b_k][b_n8]     = rb0;
        *(float4*)&Bs[0][b_k][b_n8 + 4] = rb1;
    }
    __syncthreads();

    for (int c = 0; c < NKCH; c++) {
        const int buf = c & 1;
        float4 ra0, ra1, rb0, rb1;
        const bool more = (c + 1 < NKCH);
        if (more) {
            const int k0 = (c + 1) * GBK;
            ra0 = *(const float4*)(Aptr + k0);
            ra1 = *(const float4*)(Aptr + k0 + 4);
            rb0 = *(const float4*)(Wptr + (size_t)(k0 + b_k) * N);
            rb1 = *(const float4*)(Wptr + (size_t)(k0 + b_k) * N + 4);
        }
#pragma unroll
        for (int k = 0; k < GBK; k++) {
            float4 a0 = *(const float4*)&As[buf][k][ty * 8];
            float4 a1 = *(const float4*)&As[buf][k][ty * 8 + 4];
            float4 b0 = *(const float4*)&Bs[buf][k][tx * 8];
            float4 b1 = *(const float4*)&Bs[buf][k][tx * 8 + 4];
            float ra[8] = {a0.x, a0.y, a0.z, a0.w, a1.x, a1.y, a1.z, a1.w};
            float rb[8] = {b0.x, b0.y, b0.z, b0.w, b1.x, b1.y, b1.z, b1.w};
#pragma unroll
            for (int i = 0; i < 8; i++)
#pragma unroll
                for (int j = 0; j < 8; j++)
                    acc[i][j] = fmaf(ra[i], rb[j], acc[i][j]);
        }
        if (more) {
            const int nb = buf ^ 1;
            As[nb][a_k8 + 0][a_row] = ra0.x; As[nb][a_k8 + 1][a_row] = ra0.y;
            As[nb][a_k8 + 2][a_row] = ra0.z; As[nb][a_k8 + 3][a_row] = ra0.w;
            As[nb][a_k8 + 4][a_row] = ra1.x; As[nb][a_k8 + 5][a_row] = ra1.y;
            As[nb][a_k8 + 6][a_row] = ra1.z; As[nb][a_k8 + 7][a_row] = ra1.w;
            *(float4*)&Bs[nb][b_k][b_n8]     = rb0;
            *(float4*)&Bs[nb][b_k][b_n8 + 4] = rb1;
            __syncthreads();
        }
    }

#pragma unroll
    for (int i = 0; i < 8; i++) {
        int m = row0 + ty * 8 + i;
        int b = m >> 11, s = m & 2047;   // SEQ = 2048
#pragma unroll
        for (int j = 0; j < 8; j++) {
            int n = col0 + tx * 8 + j;
            float v = acc[i][j] + bias[n];
            if (HEAD_MAJOR) {
                int hh = n >> 6, d = n & 63;   // DK = 64
                out[((size_t)((b << 4) + hh) << 17) + ((size_t)s << 6) + d] = v;
            } else {
                out[(size_t)m * N + n] = v;
            }
        }
    }
}

__global__ __launch_bounds__(256, 2) void qkv_gemm_kernel(
    const float* q, const float* k, const float* v,
    const float* Wq, const float* bq,
    const float* Wk, const float* bk,
    const float* Wv, const float* bv) {
    const float *A, *W, *bias;
    float* out;
    if (blockIdx.z == 0)      { A = q; W = Wq; bias = bq; out = g_Q; }
    else if (blockIdx.z == 1) { A = k; W = Wk; bias = bk; out = g_K; }
    else                      { A = v; W = Wv; bias = bv; out = g_V; }
    sgemm_tile<true>(A, W, bias, out, HID);
}

__global__ __launch_bounds__(256, 2) void out_gemm_kernel(
    const float* Wo, const float* bo,
    const float* Wc, const float* bc, float* out) {
    const float *W, *bias;
    float* o;
    if (blockIdx.z == 0) { W = Wc; bias = bc; o = out; }                        // c first
    else                 { W = Wo; bias = bo; o = out + (size_t)MROWS * HID; }  // then h
    sgemm_tile<false>(g_M, W, bias, o, HID);
}

// ---------------------------------------------------------------------------
// Flash attention: per (b,h), 64-query blocks, 32-key tiles, online softmax.
// Improvements over R1: K stored transposed (conflict-free score reads),
// register prefetch of next K/V tile, softmax parallelized over 256 threads.
// ---------------------------------------------------------------------------
__global__ __launch_bounds__(256) void attn_kernel() {
    __shared__ float Qs[64][68];     // q-major, padded
    __shared__ float KsT[64][36];    // transposed: KsT[d][krow], padded
    __shared__ float Vs[32][68];     // k-major, padded
    __shared__ float Ss[64][36];     // scores/probs
    __shared__ float pred[256];      // partial max / partial sum
    __shared__ float mrow[64], lrow[64], arow[64];

    const int bh = blockIdx.y;
    const int q0 = blockIdx.x * 64;
    const float* Qh = g_Q + (size_t)bh * HEADSZ;
    const float* Kh = g_K + (size_t)bh * HEADSZ;
    const float* Vh = g_V + (size_t)bh * HEADSZ;
    const int tid = threadIdx.x;
    const int tx = tid & 15, ty = tid >> 4;

    // Load Q tile (scaled by 1/sqrt(DK) = 0.125)
    for (int i = tid; i < 64 * 16; i += 256) {
        int r = i >> 4, c4 = (i & 15) << 2;
        float4 v = *(const float4*)(Qh + (size_t)(q0 + r) * DKDIM + c4);
        Qs[r][c4 + 0] = v.x * 0.125f;
        Qs[r][c4 + 1] = v.y * 0.125f;
        Qs[r][c4 + 2] = v.z * 0.125f;
        Qs[r][c4 + 3] = v.w * 0.125f;
    }
    if (tid < 64) { mrow[tid] = -1e30f; lrow[tid] = 0.f; }

    float acc[4][4];
#pragma unroll
    for (int i = 0; i < 4; i++)
#pragma unroll
        for (int j = 0; j < 4; j++) acc[i][j] = 0.f;

    // prefetch mapping: t in {0,1}: idx = tid + t*256; r = idx>>4, c4 = (idx&15)*4
    float4 kreg[2], vreg[2];
#pragma unroll
    for (int t = 0; t < 2; t++) {
        int idx = tid + t * 256;
        int r = idx >> 4, c4 = (idx & 15) << 2;
        kreg[t] = *(const float4*)(Kh + (size_t)r * DKDIM + c4);
        vreg[t] = *(const float4*)(Vh + (size_t)r * DKDIM + c4);
    }
    __syncthreads();   // Qs ready

    const int row = tid & 63, part = tid >> 6;   // softmax mapping
    const int cbase = part * 8;

    for (int c = 0; c < SEQ / 32; c++) {
        // store prefetched K/V regs to smem (K transposed)
#pragma unroll
        for (int t = 0; t < 2; t++) {
            int idx = tid + t * 256;
            int r = idx >> 4, c4 = (idx & 15) << 2;
            *(float4*)&Vs[r][c4] = vreg[t];
            KsT[c4 + 0][r] = kreg[t].x;
            KsT[c4 + 1][r] = kreg[t].y;
            KsT[c4 + 2][r] = kreg[t].z;
            KsT[c4 + 3][r] = kreg[t].w;
        }
        __syncthreads();   // S1: tiles visible

        // issue next tile's loads (latency hidden behind phases A-C)
        if (c + 1 < SEQ / 32) {
            const int k0 = (c + 1) * 32;
#pragma unroll
            for (int t = 0; t < 2; t++) {
                int idx = tid + t * 256;
                int r = idx >> 4, c4 = (idx & 15) << 2;
                kreg[t] = *(const float4*)(Kh + (size_t)(k0 + r) * DKDIM + c4);
                vreg[t] = *(const float4*)(Vh + (size_t)(k0 + r) * DKDIM + c4);
            }
        }

        // Phase A: scores S = Qs * K^T (4q x 2k per thread), conflict-free
        {
            const int qb = ty * 4, kb = tx * 2;
            float s00 = 0, s01 = 0, s10 = 0, s11 = 0;
            float s20 = 0, s21 = 0, s30 = 0, s31 = 0;
#pragma unroll 8
            for (int d = 0; d < DKDIM; d++) {
                float b0 = KsT[d][kb], b1 = KsT[d][kb + 1];
                float a0 = Qs[qb + 0][d]; s00 = fmaf(a0, b0, s00); s01 = fmaf(a0, b1, s01);
                float a1 = Qs[qb + 1][d]; s10 = fmaf(a1, b0, s10); s11 = fmaf(a1, b1, s11);
                float a2 = Qs[qb + 2][d]; s20 = fmaf(a2, b0, s20); s21 = fmaf(a2, b1, s21);
                float a3 = Qs[qb + 3][d]; s30 = fmaf(a3, b0, s30); s31 = fmaf(a3, b1, s31);
            }
            Ss[qb + 0][kb] = s00; Ss[qb + 0][kb + 1] = s01;
            Ss[qb + 1][kb] = s10; Ss[qb + 1][kb + 1] = s11;
            Ss[qb + 2][kb] = s20; Ss[qb + 2][kb + 1] = s21;
            Ss[qb + 3][kb] = s30; Ss[qb + 3][kb + 1] = s31;
        }
        __syncthreads();   // S2: scores ready

        // Phase B: online softmax, parallel over all 256 threads
        {
            float pm = -1e30f;
#pragma unroll
            for (int j = 0; j < 8; j++) pm = fmaxf(pm, Ss[row][cbase + j]);
            pred[tid] = pm;
        }
        __syncthreads();   // S3: partial maxes
        if (tid < 64) {
            float mo = mrow[tid];
            float m = fmaxf(fmaxf(pred[tid], pred[tid + 64]),
                            fmaxf(pred[tid + 128], pred[tid + 192]));
            m = fmaxf(m, mo);
            mrow[tid] = m;
            arow[tid] = __expf(mo - m);
        }
        __syncthreads();   // S4: mrow/arow final
        {
            float mm = mrow[row];
            float s = 0.f;
#pragma unroll
            for (int j = 0; j < 8; j++) {
                float p = __expf(Ss[row][cbase + j] - mm);
                Ss[row][cbase + j] = p;
                s += p;
            }
            pred[tid] = s;
        }
        __syncthreads();   // S5: probs + partial sums ready
        if (tid < 64) {
            lrow[tid] = lrow[tid] * arow[tid] +
                        (pred[tid] + pred[tid + 64]) +
                        (pred[tid + 128] + pred[tid + 192]);
        }

        // Phase C: acc = acc*alpha + P * V  (4q x 4d per thread)
        {
            const int qb = ty * 4, db = tx * 4;
            float al0 = arow[qb], al1 = arow[qb + 1], al2 = arow[qb + 2], al3 = arow[qb + 3];
#pragma unroll
            for (int j = 0; j < 4; j++) {
                acc[0][j] *= al0; acc[1][j] *= al1;
                acc[2][j] *= al2; acc[3][j] *= al3;
            }
#pragma unroll 4
            for (int j = 0; j < 32; j++) {
                float4 vv = *(const float4*)&Vs[j][db];
                float p0 = Ss[qb + 0][j], p1 = Ss[qb + 1][j];
                float p2 = Ss[qb + 2][j], p3 = Ss[qb + 3][j];
                acc[0][0] = fmaf(p0, vv.x, acc[0][0]); acc[0][1] = fmaf(p0, vv.y, acc[0][1]);
                acc[0][2] = fmaf(p0, vv.z, acc[0][2]); acc[0][3] = fmaf(p0, vv.w, acc[0][3]);
                acc[1][0] = fmaf(p1, vv.x, acc[1][0]); acc[1][1] = fmaf(p1, vv.y, acc[1][1]);
                acc[1][2] = fmaf(p1, vv.z, acc[1][2]); acc[1][3] = fmaf(p1, vv.w, acc[1][3]);
                acc[2][0] = fmaf(p2, vv.x, acc[2][0]); acc[2][1] = fmaf(p2, vv.y, acc[2][1]);
                acc[2][2] = fmaf(p2, vv.z, acc[2][2]); acc[2][3] = fmaf(p2, vv.w, acc[2][3]);
                acc[3][0] = fmaf(p3, vv.x, acc[3][0]); acc[3][1] = fmaf(p3, vv.y, acc[3][1]);
                acc[3][2] = fmaf(p3, vv.z, acc[3][2]); acc[3][3] = fmaf(p3, vv.w, acc[3][3]);
            }
        }
        __syncthreads();   // S6: Vs/KsT/Ss consumed; lrow final
    }

    // Normalize and write merged [MROWS][HID]: col = h*64 + d
    {
        const int qb = ty * 4, db = tx * 4;
        const int b = bh >> 4, hh = bh & 15;
#pragma unroll
        for (int i = 0; i < 4; i++) {
            float inv = 1.0f / lrow[qb + i];
            float4 o;
            o.x = acc[i][0] * inv; o.y = acc[i][1] * inv;
            o.z = acc[i][2] * inv; o.w = acc[i][3] * inv;
            *(float4*)(g_M + (size_t)(b * SEQ + q0 + qb + i) * HID + hh * DKDIM + db) = o;
        }
    }
}

// ---------------------------------------------------------------------------
extern "C" void kernel_launch(void* const* d_in, const int* in_sizes, int n_in,
                              void* d_out, int out_size) {
    const float* q  = (const float*)d_in[0];
    const float* k  = (const float*)d_in[1];
    const float* v  = (const float*)d_in[2];
    const float* Wq = (const float*)d_in[3];
    const float* bq = (const float*)d_in[4];
    const float* Wk = (const float*)d_in[5];
    const float* bk = (const float*)d_in[6];
    const float* Wv = (const float*)d_in[7];
    const float* bv = (const float*)d_in[8];
    const float* Wo = (const float*)d_in[9];
    const float* bo = (const float*)d_in[10];
    const float* Wc = (const float*)d_in[11];
    const float* bc = (const float*)d_in[12];
    float* out = (float*)d_out;

    dim3 g1(HID / GBN, MROWS / GBM, 3);
    qkv_gemm_kernel<<<g1, 256>>>(q, k, v, Wq, bq, Wk, bk, Wv, bv);

    attn_kernel<<<dim3(SEQ / 64, BATCH * NHEAD), 256>>>();

    dim3 g2(HID / GBN, MROWS / GBM, 2);
    out_gemm_kernel<<<g2, 256>>>(Wo, bo, Wc, bc, out);
}

// round 9
// speedup vs baseline: 1.2924x; 1.1722x over previous
#include <cuda_runtime.h>
#include <cstdint>

// Problem constants
#define HID   1024
#define NHEAD 16
#define DKDIM 64
#define SEQ   2048
#define BATCH 2
#define MROWS (BATCH * SEQ)      // 4096
#define HEADSZ (SEQ * DKDIM)     // 131072 floats per (b,h) head

// Scratch (allocation-free rule: __device__ globals)
__device__ float g_Q[MROWS * HID];   // head-major [B*NH][SEQ][DK]
__device__ float g_K[MROWS * HID];
__device__ float g_V[MROWS * HID];
__device__ float g_M[MROWS * HID];   // merged attention output [MROWS][HID]

// ---------------------------------------------------------------------------
// SGEMM: C[M,N] = A[M,K=1024] * W[1024,N] + bias
// 128x128 tile, GBK=16, register-staged double buffer, 1 sync per chunk.
// B fragments at {tx*4, 64+tx*4}: stride-4 => conflict-free LDS.128.
// ---------------------------------------------------------------------------
#define GBM 128
#define GBN 128
#define GBK 16
#define NKCH (HID / GBK)   // 64

template<bool HEAD_MAJOR>
__device__ __forceinline__ void sgemm_tile(const float* __restrict__ A,
                                           const float* __restrict__ W,
                                           const float* __restrict__ bias,
                                           float* __restrict__ out, int N) {
    __shared__ float As[2][GBK][GBM];   // 16 KB
    __shared__ float Bs[2][GBK][GBN];   // 16 KB
    const int tid = threadIdx.x;
    const int tx = tid & 15, ty = tid >> 4;
    const int row0 = blockIdx.y * GBM;
    const int col0 = blockIdx.x * GBN;

    // A loader: row = tid/2, k-offset = (tid&1)*8, two float4s
    const int a_row = tid >> 1;
    const int a_k8  = (tid & 1) * 8;
    // B loader: k-row = tid/16 (0..15), n-offsets {b_n4, 64+b_n4}
    const int b_k  = tid >> 4;
    const int b_n4 = (tid & 15) * 4;

    const float* Aptr = A + (size_t)(row0 + a_row) * HID + a_k8;
    const float* Wptr = W + col0 + b_n4;   // + k*N per chunk

    float acc[8][8];
#pragma unroll
    for (int i = 0; i < 8; i++)
#pragma unroll
        for (int j = 0; j < 8; j++) acc[i][j] = 0.f;

    // preamble: chunk 0 -> smem[0]
    {
        float4 ra0 = *(const float4*)(Aptr + 0);
        float4 ra1 = *(const float4*)(Aptr + 4);
        float4 rb0 = *(const float4*)(Wptr + (size_t)b_k * N);
        float4 rb1 = *(const float4*)(Wptr + (size_t)b_k * N + 64);
        As[0][a_k8 + 0][a_row] = ra0.x; As[0][a_k8 + 1][a_row] = ra0.y;
        As[0][a_k8 + 2][a_row] = ra0.z; As[0][a_k8 + 3][a_row] = ra0.w;
        As[0][a_k8 + 4][a_row] = ra1.x; As[0][a_k8 + 5][a_row] = ra1.y;
        As[0][a_k8 + 6][a_row] = ra1.z; As[0][a_k8 + 7][a_row] = ra1.w;
        *(float4*)&Bs[0][b_k][b_n4]      = rb0;
        *(float4*)&Bs[0][b_k][b_n4 + 64] = rb1;
    }
    __syncthreads();

    for (int c = 0; c < NKCH; c++) {
        const int buf = c & 1;
        float4 ra0, ra1, rb0, rb1;
        const bool more = (c + 1 < NKCH);
        if (more) {
            const int k0 = (c + 1) * GBK;
            ra0 = *(const float4*)(Aptr + k0);
            ra1 = *(const float4*)(Aptr + k0 + 4);
            rb0 = *(const float4*)(Wptr + (size_t)(k0 + b_k) * N);
            rb1 = *(const float4*)(Wptr + (size_t)(k0 + b_k) * N + 64);
        }
#pragma unroll
        for (int k = 0; k < GBK; k++) {
            float4 a0 = *(const float4*)&As[buf][k][ty * 8];
            float4 a1 = *(const float4*)&As[buf][k][ty * 8 + 4];
            float4 b0 = *(const float4*)&Bs[buf][k][tx * 4];
            float4 b1 = *(const float4*)&Bs[buf][k][64 + tx * 4];
            float ra[8] = {a0.x, a0.y, a0.z, a0.w, a1.x, a1.y, a1.z, a1.w};
            float rb[8] = {b0.x, b0.y, b0.z, b0.w, b1.x, b1.y, b1.z, b1.w};
#pragma unroll
            for (int i = 0; i < 8; i++)
#pragma unroll
                for (int j = 0; j < 8; j++)
                    acc[i][j] = fmaf(ra[i], rb[j], acc[i][j]);
        }
        if (more) {
            const int nb = buf ^ 1;
            As[nb][a_k8 + 0][a_row] = ra0.x; As[nb][a_k8 + 1][a_row] = ra0.y;
            As[nb][a_k8 + 2][a_row] = ra0.z; As[nb][a_k8 + 3][a_row] = ra0.w;
            As[nb][a_k8 + 4][a_row] = ra1.x; As[nb][a_k8 + 5][a_row] = ra1.y;
            As[nb][a_k8 + 6][a_row] = ra1.z; As[nb][a_k8 + 7][a_row] = ra1.w;
            *(float4*)&Bs[nb][b_k][b_n4]      = rb0;
            *(float4*)&Bs[nb][b_k][b_n4 + 64] = rb1;
            __syncthreads();
        }
    }

#pragma unroll
    for (int i = 0; i < 8; i++) {
        int m = row0 + ty * 8 + i;
        int b = m >> 11, s = m & 2047;   // SEQ = 2048
#pragma unroll
        for (int j = 0; j < 8; j++) {
            int n = col0 + ((j < 4) ? (tx * 4 + j) : (64 + tx * 4 + j - 4));
            float v = acc[i][j] + bias[n];
            if (HEAD_MAJOR) {
                int hh = n >> 6, d = n & 63;   // DK = 64
                out[((size_t)((b << 4) + hh) << 17) + ((size_t)s << 6) + d] = v;
            } else {
                out[(size_t)m * N + n] = v;
            }
        }
    }
}

__global__ __launch_bounds__(256, 2) void qkv_gemm_kernel(
    const float* q, const float* k, const float* v,
    const float* Wq, const float* bq,
    const float* Wk, const float* bk,
    const float* Wv, const float* bv) {
    const float *A, *W, *bias;
    float* out;
    if (blockIdx.z == 0)      { A = q; W = Wq; bias = bq; out = g_Q; }
    else if (blockIdx.z == 1) { A = k; W = Wk; bias = bk; out = g_K; }
    else                      { A = v; W = Wv; bias = bv; out = g_V; }
    sgemm_tile<true>(A, W, bias, out, HID);
}

__global__ __launch_bounds__(256, 2) void out_gemm_kernel(
    const float* Wo, const float* bo,
    const float* Wc, const float* bc, float* out) {
    const float *W, *bias;
    float* o;
    if (blockIdx.z == 0) { W = Wc; bias = bc; o = out; }                        // c first
    else                 { W = Wo; bias = bo; o = out + (size_t)MROWS * HID; }  // then h
    sgemm_tile<false>(g_M, W, bias, o, HID);
}

// ---------------------------------------------------------------------------
// Flash attention, 64q x 64k tiles. 256 threads = (tx=16, ty=16).
// Thread tile: scores 4q x 4k in registers; PV acc 4q x 4d.
// QsT/KsT transposed => phase A is 2x LDS.128 (one broadcast) per d.
// Softmax in registers via shfl_xor over the 16-lane tx group.
// U buffer: K^T during phase A, then P (probs) for phase C. Smem = 48KB.
// ---------------------------------------------------------------------------
__global__ __launch_bounds__(256) void attn_kernel() {
    __shared__ float QsT[64 * 64];   // [d][q]
    __shared__ float U[64 * 64];     // K^T [d][k] -> P [q][k]
    __shared__ float Vs[64 * 64];    // [k][d]

    const int bh = blockIdx.y;
    const int q0 = blockIdx.x * 64;
    const float* Qh = g_Q + (size_t)bh * HEADSZ;
    const float* Kh = g_K + (size_t)bh * HEADSZ;
    const float* Vh = g_V + (size_t)bh * HEADSZ;
    const int tid = threadIdx.x;
    const int tx = tid & 15, ty = tid >> 4;

    // Load Q transposed + scaled. idx -> (q = idx&63, d4 = (idx>>6)*4)
#pragma unroll
    for (int t = 0; t < 4; t++) {
        int idx = tid + t * 256;
        int r = idx & 63, c4 = (idx >> 6) << 2;
        float4 v = *(const float4*)(Qh + (size_t)(q0 + r) * DKDIM + c4);
        QsT[(c4 + 0) * 64 + r] = v.x * 0.125f;
        QsT[(c4 + 1) * 64 + r] = v.y * 0.125f;
        QsT[(c4 + 2) * 64 + r] = v.z * 0.125f;
        QsT[(c4 + 3) * 64 + r] = v.w * 0.125f;
    }

    float m[4], l[4], acc[4][4];
#pragma unroll
    for (int i = 0; i < 4; i++) {
        m[i] = -1e30f; l[i] = 0.f;
#pragma unroll
        for (int j = 0; j < 4; j++) acc[i][j] = 0.f;
    }

    // prefetch tile 0 into regs: K via transpose mapping, V coalesced
    float4 kreg[4], vreg[4];
#pragma unroll
    for (int t = 0; t < 4; t++) {
        int idx = tid + t * 256;
        int rk = idx & 63, ck = (idx >> 6) << 2;
        kreg[t] = *(const float4*)(Kh + (size_t)rk * DKDIM + ck);
        int rv = idx >> 4, cv = (idx & 15) << 2;
        vreg[t] = *(const float4*)(Vh + (size_t)rv * DKDIM + cv);
    }
    __syncthreads();   // QsT visible

    for (int c = 0; c < SEQ / 64; c++) {
        // store prefetched K (transposed) and V
#pragma unroll
        for (int t = 0; t < 4; t++) {
            int idx = tid + t * 256;
            int rk = idx & 63, ck = (idx >> 6) << 2;
            U[(ck + 0) * 64 + rk] = kreg[t].x;
            U[(ck + 1) * 64 + rk] = kreg[t].y;
            U[(ck + 2) * 64 + rk] = kreg[t].z;
            U[(ck + 3) * 64 + rk] = kreg[t].w;
            int rv = idx >> 4, cv = (idx & 15) << 2;
            *(float4*)(Vs + rv * 64 + cv) = vreg[t];
        }
        __syncthreads();   // S1: tiles visible

        if (c + 1 < SEQ / 64) {
            const int k0 = (c + 1) * 64;
#pragma unroll
            for (int t = 0; t < 4; t++) {
                int idx = tid + t * 256;
                int rk = idx & 63, ck = (idx >> 6) << 2;
                kreg[t] = *(const float4*)(Kh + (size_t)(k0 + rk) * DKDIM + ck);
                int rv = idx >> 4, cv = (idx & 15) << 2;
                vreg[t] = *(const float4*)(Vh + (size_t)(k0 + rv) * DKDIM + cv);
            }
        }

        // Phase A: scores (4q x 4k) in registers
        float s[4][4];
#pragma unroll
        for (int i = 0; i < 4; i++)
#pragma unroll
            for (int j = 0; j < 4; j++) s[i][j] = 0.f;
#pragma unroll 8
        for (int d = 0; d < 64; d++) {
            float4 qv = *(const float4*)(QsT + d * 64 + ty * 4);
            float4 kv = *(const float4*)(U + d * 64 + tx * 4);
            s[0][0] = fmaf(qv.x, kv.x, s[0][0]); s[0][1] = fmaf(qv.x, kv.y, s[0][1]);
            s[0][2] = fmaf(qv.x, kv.z, s[0][2]); s[0][3] = fmaf(qv.x, kv.w, s[0][3]);
            s[1][0] = fmaf(qv.y, kv.x, s[1][0]); s[1][1] = fmaf(qv.y, kv.y, s[1][1]);
            s[1][2] = fmaf(qv.y, kv.z, s[1][2]); s[1][3] = fmaf(qv.y, kv.w, s[1][3]);
            s[2][0] = fmaf(qv.z, kv.x, s[2][0]); s[2][1] = fmaf(qv.z, kv.y, s[2][1]);
            s[2][2] = fmaf(qv.z, kv.z, s[2][2]); s[2][3] = fmaf(qv.z, kv.w, s[2][3]);
            s[3][0] = fmaf(qv.w, kv.x, s[3][0]); s[3][1] = fmaf(qv.w, kv.y, s[3][1]);
            s[3][2] = fmaf(qv.w, kv.z, s[3][2]); s[3][3] = fmaf(qv.w, kv.w, s[3][3]);
        }

        // Online softmax in registers (replicated across tx via shuffles)
        float alpha[4];
#pragma unroll
        for (int i = 0; i < 4; i++) {
            float rm = fmaxf(fmaxf(s[i][0], s[i][1]), fmaxf(s[i][2], s[i][3]));
#pragma unroll
            for (int o = 8; o >= 1; o >>= 1)
                rm = fmaxf(rm, __shfl_xor_sync(0xffffffffu, rm, o));
            float mn = fmaxf(m[i], rm);
            alpha[i] = __expf(m[i] - mn);
            m[i] = mn;
            s[i][0] = __expf(s[i][0] - mn);
            s[i][1] = __expf(s[i][1] - mn);
            s[i][2] = __expf(s[i][2] - mn);
            s[i][3] = __expf(s[i][3] - mn);
            float rs = (s[i][0] + s[i][1]) + (s[i][2] + s[i][3]);
#pragma unroll
            for (int o = 8; o >= 1; o >>= 1)
                rs += __shfl_xor_sync(0xffffffffu, rs, o);
            l[i] = l[i] * alpha[i] + rs;
        }
        __syncthreads();   // S2: all K^T reads done before P overwrites U

        // write P
#pragma unroll
        for (int i = 0; i < 4; i++) {
            float4 pv = {s[i][0], s[i][1], s[i][2], s[i][3]};
            *(float4*)(U + (ty * 4 + i) * 64 + tx * 4) = pv;
        }
        __syncthreads();   // S3: P visible

        // Phase C: acc = acc*alpha + P * V (4q x 4d, d-cols = tx*4..)
#pragma unroll
        for (int i = 0; i < 4; i++)
#pragma unroll
            for (int j = 0; j < 4; j++) acc[i][j] *= alpha[i];
#pragma unroll 4
        for (int j = 0; j < 64; j++) {
            float4 vv = *(const float4*)(Vs + j * 64 + tx * 4);
            float p0 = U[(ty * 4 + 0) * 64 + j];
            float p1 = U[(ty * 4 + 1) * 64 + j];
            float p2 = U[(ty * 4 + 2) * 64 + j];
            float p3 = U[(ty * 4 + 3) * 64 + j];
            acc[0][0] = fmaf(p0, vv.x, acc[0][0]); acc[0][1] = fmaf(p0, vv.y, acc[0][1]);
            acc[0][2] = fmaf(p0, vv.z, acc[0][2]); acc[0][3] = fmaf(p0, vv.w, acc[0][3]);
            acc[1][0] = fmaf(p1, vv.x, acc[1][0]); acc[1][1] = fmaf(p1, vv.y, acc[1][1]);
            acc[1][2] = fmaf(p1, vv.z, acc[1][2]); acc[1][3] = fmaf(p1, vv.w, acc[1][3]);
            acc[2][0] = fmaf(p2, vv.x, acc[2][0]); acc[2][1] = fmaf(p2, vv.y, acc[2][1]);
            acc[2][2] = fmaf(p2, vv.z, acc[2][2]); acc[2][3] = fmaf(p2, vv.w, acc[2][3]);
            acc[3][0] = fmaf(p3, vv.x, acc[3][0]); acc[3][1] = fmaf(p3, vv.y, acc[3][1]);
            acc[3][2] = fmaf(p3, vv.z, acc[3][2]); acc[3][3] = fmaf(p3, vv.w, acc[3][3]);
        }
        __syncthreads();   // S4: U/Vs consumed before next tile store
    }

    // Normalize and write merged [MROWS][HID]: col = h*64 + d
    {
        const int b = bh >> 4, hh = bh & 15;
#pragma unroll
        for (int i = 0; i < 4; i++) {
            float inv = 1.0f / l[i];
            float4 o;
            o.x = acc[i][0] * inv; o.y = acc[i][1] * inv;
            o.z = acc[i][2] * inv; o.w = acc[i][3] * inv;
            *(float4*)(g_M + (size_t)(b * SEQ + q0 + ty * 4 + i) * HID
                       + hh * DKDIM + tx * 4) = o;
        }
    }
}

// ---------------------------------------------------------------------------
extern "C" void kernel_launch(void* const* d_in, const int* in_sizes, int n_in,
                              void* d_out, int out_size) {
    const float* q  = (const float*)d_in[0];
    const float* k  = (const float*)d_in[1];
    const float* v  = (const float*)d_in[2];
    const float* Wq = (const float*)d_in[3];
    const float* bq = (const float*)d_in[4];
    const float* Wk = (const float*)d_in[5];
    const float* bk = (const float*)d_in[6];
    const float* Wv = (const float*)d_in[7];
    const float* bv = (const float*)d_in[8];
    const float* Wo = (const float*)d_in[9];
    const float* bo = (const float*)d_in[10];
    const float* Wc = (const float*)d_in[11];
    const float* bc = (const float*)d_in[12];
    float* out = (float*)d_out;

    dim3 g1(HID / GBN, MROWS / GBM, 3);
    qkv_gemm_kernel<<<g1, 256>>>(q, k, v, Wq, bq, Wk, bk, Wv, bv);

    attn_kernel<<<dim3(SEQ / 64, BATCH * NHEAD), 256>>>();

    dim3 g2(HID / GBN, MROWS / GBM, 2);
    out_gemm_kernel<<<g2, 256>>>(Wo, bo, Wc, bc, out);
}